// round 13
// baseline (speedup 1.0000x reference)
#include <cuda_runtime.h>
#include <math.h>

#define NN    8192
#define HN    4096
#define QN    2048
#define MODES 16
#define ROWS  4096          /* BATCH*CH */
#define KSPL  8             /* forward m-splits */
#define MSPL  256           /* m per split = QN/KSPL */

/* fwd combo smem: [cls][m][row], 64 rows/block */
#define CMB_T 68            /* 64 rows + pad; T mod 32 = 4, T mod 4 = 0 */
#define CMB_S 2184          /* 32*68+8;      S mod 32 = 8, S mod 4 = 0 */

// Scratch (__device__ globals: allocation-free rule)
__device__ float g_FBf[QN*32];             // fwd basis, grouped, x0.5 at m=0
__device__ float g_FBi[QN*32];             // inv basis, grouped
__device__ float g_partial[KSPL*32*ROWS];  // fwd partials TRANSPOSED [ks][c][row]
__device__ float g_C2[ROWS*32];            // irfft coefs, grouped A/B
__device__ float g_WrT[MODES*4096];        // weights transposed: [k][i*64+o]
__device__ float g_WiT[MODES*4096];

// Grouped column layout c' = 0..31:
//   j = c'&7, odd = (c'>>3)&1, k = 2j+odd
//   c' 0..7: cos even k   8..15: cos odd   16..23: sin even   24..31: sin odd
__global__ void init_tables(const float* __restrict__ wr,
                            const float* __restrict__ wi) {
    int idx = blockIdx.x * blockDim.x + threadIdx.x;
    if (idx >= QN * 32) return;   // 65536 == basis entries == weight entries
    {   // basis
        int m = idx >> 5, c = idx & 31;
        int j = c & 7;
        int kk = 2 * j + ((c >> 3) & 1);
        int t = (kk * m) & (NN - 1);
        float a = (float)t * (1.0f / (float)HN);
        float v = (c < 16) ? cospif(a) : sinpif(a);
        g_FBi[idx] = v;
        g_FBf[idx] = (m == 0) ? 0.5f * v : v;  // m=0 quartet double-counts x[0],x[4096]
    }
    {   // weight transpose: wr[(i*64+o)*16+k] -> g_WrT[k][i*64+o]
        int io = idx >> 4, k = idx & 15;
        g_WrT[k * 4096 + io] = wr[idx];
        g_WiT[k * 4096 + io] = wi[idx];
    }
}

// ---------------------------------------------------------------------------
// Forward (folded): partial_T[ks][c'][row] = sum_m combo_{cls}[row][m]*FBf[m][c']
// PROVEN tile: 64 rows/block, 128 threads, 4r x 4c; inner 2x LDS.128 + 16 FFMA,
// register double-buffered. KSPL=8 -> 512 blocks.
// ks==0 blocks add the m=2048 boundary term. Epilogue stores TRANSPOSED
// [ks][c][row] as STG.128 over the thread's 4 rows (keeps mixred coalesced).
// ---------------------------------------------------------------------------
__global__ __launch_bounds__(128) void fwd_dft(const float* __restrict__ x) {
    __shared__ float  cmb[4 * CMB_S];     // 34.9 KB
    __shared__ float4 bs[32][8];          // 4 KB

    const int tid  = threadIdx.x;
    const int row0 = blockIdx.x * 64;
    const int ms0  = blockIdx.y * MSPL;
    const int tr   = tid >> 3;            // 0..15 -> rows 4*tr..4*tr+3
    const int tc   = tid & 7;             // 0..7  -> cols 4*tc..4*tc+3
    const int cls  = tc >> 1;             // 0..3

    float acc[4][4];
    #pragma unroll
    for (int j = 0; j < 4; j++)
        #pragma unroll
        for (int q = 0; q < 4; q++) acc[j][q] = 0.f;

    for (int ch = 0; ch < MSPL / 32; ch++) {
        const int m0 = ms0 + ch * 32;

        // stage combos: thread (row, g) covers m = g + 8*jj; conflict-free STS
        #pragma unroll
        for (int i = 0; i < 4; i++) {
            int q   = tid + i * 128;
            int row = q >> 3;
            int g   = q & 7;
            const float* xr = x + (size_t)(row0 + row) * NN;
            #pragma unroll
            for (int jj = 0; jj < 4; jj++) {
                int mi = g + 8 * jj;
                int mm = m0 + mi;
                float v0 = xr[mm];
                float v1 = xr[HN - mm];
                float v2 = xr[HN + mm];
                float v3 = xr[(NN - mm) & (NN - 1)];
                float p = v0 + v3, q2 = v0 - v3;
                float r = v1 + v2, s  = v2 - v1;
                float* base = cmb + mi * CMB_T + row;
                base[0 * CMB_S] = p + r;    // even-cos
                base[1 * CMB_S] = p - r;    // odd-cos
                base[2 * CMB_S] = q2 + s;   // even-sin
                base[3 * CMB_S] = q2 - s;   // odd-sin
            }
        }
        // stage basis tile (32 m x 32 c)
        #pragma unroll
        for (int i = 0; i < 2; i++) {
            int q  = tid + i * 128;
            int k  = q >> 3;
            int cq = q & 7;
            bs[k][cq] = *(const float4*)(g_FBf + (size_t)(m0 + k) * 32 + 4 * cq);
        }
        __syncthreads();

        const float* cbase = cmb + cls * CMB_S + 4 * tr;
        float4 xv = *(const float4*)(cbase);
        float4 bv = bs[0][tc];
        #pragma unroll
        for (int m = 0; m < 32; m++) {
            float4 xvn, bvn;
            if (m < 31) {                       // register double-buffer
                xvn = *(const float4*)(cbase + (m + 1) * CMB_T);
                bvn = bs[m + 1][tc];
            }
            acc[0][0] += xv.x * bv.x; acc[0][1] += xv.x * bv.y;
            acc[0][2] += xv.x * bv.z; acc[0][3] += xv.x * bv.w;
            acc[1][0] += xv.y * bv.x; acc[1][1] += xv.y * bv.y;
            acc[1][2] += xv.y * bv.z; acc[1][3] += xv.y * bv.w;
            acc[2][0] += xv.z * bv.x; acc[2][1] += xv.z * bv.y;
            acc[2][2] += xv.z * bv.z; acc[2][3] += xv.z * bv.w;
            acc[3][0] += xv.w * bv.x; acc[3][1] += xv.w * bv.y;
            acc[3][2] += xv.w * bv.z; acc[3][3] += xv.w * bv.w;
            xv = xvn; bv = bvn;
        }
        __syncthreads();
    }

    // m=2048 boundary (only ks==0 blocks): c<8 (cos even k=2j): (xa+xb)*(-1)^j
    //                                      c>=24 (sin odd k):   (xa-xb)*(-1)^j
    if (blockIdx.y == 0 && (tc < 2 || tc >= 6)) {
        #pragma unroll
        for (int j = 0; j < 4; j++) {
            const float* xr = x + (size_t)(row0 + 4 * tr + j) * NN;
            float xa = xr[QN], xb = xr[3 * QN];
            float t  = (tc < 2) ? (xa + xb) : (xa - xb);
            #pragma unroll
            for (int q = 0; q < 4; q++) {
                int cj = (4 * tc + q) & 7;
                acc[j][q] += (cj & 1) ? -t : t;
            }
        }
    }

    // epilogue: transposed store [ks][c][row] -- STG.128 over the 4 rows
    #pragma unroll
    for (int q = 0; q < 4; q++) {
        int c = 4 * tc + q;
        *(float4*)(g_partial + ((size_t)blockIdx.y * 32 + c) * ROWS + row0 + 4 * tr)
            = make_float4(acc[0][q], acc[1][q], acc[2][q], acc[3][q]);
    }
}

// ---------------------------------------------------------------------------
// Fused reduce + mix: grid (16 k, 16 bg), 256 thr. Reduces the K-splits with
// fully coalesced reads from the transposed partials (256 consecutive rows per
// column), then applies complex weights from smem-staged transposed copies.
// ---------------------------------------------------------------------------
__global__ __launch_bounds__(256) void mixred() {
    __shared__ float sWr[64 * 64];
    __shared__ float sWi[64 * 64];
    __shared__ float sXc[256], sXs[256];
    const int k   = blockIdx.x;
    const int bg  = blockIdx.y;
    const int tid = threadIdx.x;

    const int cA = (k & 1) ? 8 + (k >> 1) : (k >> 1);
    const int cS = cA + 16;

    const float* wrk = g_WrT + (size_t)k * 4096;
    const float* wik = g_WiT + (size_t)k * 4096;
    #pragma unroll
    for (int i = 0; i < 4; i++) {
        int q = tid + i * 256;
        ((float4*)sWr)[q] = ((const float4*)wrk)[q];
        ((float4*)sWi)[q] = ((const float4*)wik)[q];
    }
    {   // fused K-split reduction, coalesced: row = bg*256 + tid
        int row = bg * 256 + tid;
        float xc = 0.f, xs = 0.f;
        #pragma unroll
        for (int ks = 0; ks < KSPL; ks++) {
            xc += g_partial[((size_t)ks * 32 + cA) * ROWS + row];
            xs += g_partial[((size_t)ks * 32 + cS) * ROWS + row];
        }
        sXc[tid] = xc;
        sXs[tid] = xs;
    }
    __syncthreads();

    const int o  = tid & 63;
    const int bl = tid >> 6;
    float cre = 0.f, cim = 0.f;
    #pragma unroll 8
    for (int i = 0; i < 64; i++) {
        float a   = sXc[bl * 64 + i];
        float s   = sXs[bl * 64 + i];
        float wre = sWr[i * 64 + o];
        float wim = sWi[i * 64 + o];
        cre += a * wre + s * wim;
        cim += a * wim - s * wre;
    }
    const float invN = 1.0f / (float)NN;
    float A  = (k == 0 ? cre : 2.f * cre) * invN;
    float Bc = (k == 0 ? 0.f : -2.f * cim * invN);
    int rowo = (bg * 4 + bl) * 64 + o;
    g_C2[(size_t)rowo * 32 + cA] = A;
    g_C2[(size_t)rowo * 32 + cS] = Bc;
}

// ---------------------------------------------------------------------------
// Inverse (folded): SPREAD-n -- thread owns n1 = idx (0..1023), n2 = n1+1024;
// all 8 scalar stores warp-coalesced. Group-accumulator consumption, ~110 regs.
// 128 thr, 32 rows/block -> 1024 blocks. n=0 wraps are exact duplicates;
// n1==0 emits n=2048/6144. (Measured R12: 34.8us.)
// ---------------------------------------------------------------------------
__global__ __launch_bounds__(128) void inv_dft(float* __restrict__ y) {
    __shared__ float sC[32 * 32];
    const int tid  = threadIdx.x;
    const int row0 = blockIdx.y * 32;
    const int n1   = blockIdx.x * 128 + tid;    // 0..1023
    const int n2   = n1 + 1024;                 // 1024..2047

    #pragma unroll
    for (int i = 0; i < 2; i++) {
        int q = tid + i * 128;
        *(float4*)(sC + 4 * q) = *(const float4*)(g_C2 + (size_t)row0 * 32 + 4 * q);
    }

    float b1[32], b2[32];
    #pragma unroll
    for (int i = 0; i < 8; i++) {
        float4 v = *(const float4*)(g_FBi + (size_t)n1 * 32 + 4 * i);
        b1[4*i+0] = v.x; b1[4*i+1] = v.y; b1[4*i+2] = v.z; b1[4*i+3] = v.w;
        float4 u = *(const float4*)(g_FBi + (size_t)n2 * 32 + 4 * i);
        b2[4*i+0] = u.x; b2[4*i+1] = u.y; b2[4*i+2] = u.z; b2[4*i+3] = u.w;
    }
    __syncthreads();

    const int nrev1 = (NN - n1) & (NN - 1);     // 0 when n1==0 (dup, benign)
    const int nm1   = HN - n1,  np1 = HN + n1;
    const int nrev2 = NN - n2;
    const int nm2   = HN - n2,  np2 = HN + n2;

    for (int r = 0; r < 32; r++) {
        const float* cp = sC + r * 32;
        // a[0]=E (cos-even), a[1]=F (cos-odd), a[2]=G (sin-even), a[3]=H (sin-odd)
        float a1[4] = {0.f, 0.f, 0.f, 0.f};
        float a2[4] = {0.f, 0.f, 0.f, 0.f};
        #pragma unroll
        for (int i = 0; i < 8; i++) {
            float4 v = *(const float4*)(cp + 4 * i);   // broadcast LDS.128
            int g = i >> 1;
            a1[g] += v.x * b1[4*i] + v.y * b1[4*i+1] + v.z * b1[4*i+2] + v.w * b1[4*i+3];
            a2[g] += v.x * b2[4*i] + v.y * b2[4*i+1] + v.z * b2[4*i+2] + v.w * b2[4*i+3];
        }
        float P1 = a1[0] + a1[1], Q1 = a1[0] - a1[1];
        float R1 = a1[2] + a1[3], S1 = a1[2] - a1[3];
        float P2 = a2[0] + a2[1], Q2 = a2[0] - a2[1];
        float R2 = a2[2] + a2[3], S2 = a2[2] - a2[3];
        size_t rb = (size_t)(row0 + r) * NN;

        y[rb + n1]    = P1 + R1;
        y[rb + nrev1] = P1 - R1;     // n1==0: dup of y[0] (R1==0), benign
        y[rb + nm1]   = Q1 - S1;     // n1==0: dup of np1 (S1==0), benign
        y[rb + np1]   = Q1 + S1;
        y[rb + n2]    = P2 + R2;
        y[rb + nrev2] = P2 - R2;
        y[rb + nm2]   = Q2 - S2;
        y[rb + np2]   = Q2 + S2;

        if (n1 == 0) {   // outputs n=2048, 6144
            float da = 0.f, db = 0.f;
            #pragma unroll
            for (int i = 0; i < 8; i++) {
                float sg = (i & 1) ? -1.f : 1.f;
                da += sg * cp[i];        // A_{2j} * (-1)^j
                db += sg * cp[24 + i];   // B_{2j+1} * (-1)^j
            }
            y[rb + QN]     = da + db;
            y[rb + 3 * QN] = da - db;
        }
    }
}

// ---------------------------------------------------------------------------
extern "C" void kernel_launch(void* const* d_in, const int* in_sizes, int n_in,
                              void* d_out, int out_size) {
    const float* x  = (const float*)d_in[0];
    const float* wr = (const float*)d_in[1];
    const float* wi = (const float*)d_in[2];
    float*       y  = (float*)d_out;

    init_tables<<<(QN * 32 + 255) / 256, 256>>>(wr, wi);
    fwd_dft<<<dim3(ROWS / 64, KSPL), 128>>>(x);
    mixred<<<dim3(MODES, 16), 256>>>();
    inv_dft<<<dim3(QN / 2 / 128, ROWS / 32), 128>>>(y);   // 4th -> profiled
}

// round 17
// speedup vs baseline: 1.3703x; 1.3703x over previous
#include <cuda_runtime.h>
#include <math.h>

#define NN    8192
#define HN    4096
#define QN    2048
#define MODES 16
#define ROWS  4096          /* BATCH*CH */
#define KSPL  8             /* forward m-splits */
#define MSPL  256           /* m per split = QN/KSPL */

/* fwd combo smem: [cls][m][row], 64 rows/block */
#define CMB_T 68            /* 64 rows + pad; T mod 32 = 4, T mod 4 = 0 */
#define CMB_S 2184          /* 32*68+8;      S mod 32 = 8, S mod 4 = 0 */

// Scratch (__device__ globals: allocation-free rule)
__device__ float g_FBf[QN*32];             // fwd basis, grouped, x0.5 at m=0
__device__ float g_FBi[QN*32];             // inv basis, grouped
__device__ float g_partial[KSPL*ROWS*32];  // fwd partials [ks][row][c] (row-major)
__device__ float g_CS[ROWS*32];            // reduced fwd sums (+boundary)
__device__ float g_C2[ROWS*32];            // irfft coefs, grouped A/B
__device__ float g_WrT[MODES*4096];        // weights transposed: [k][i*64+o]
__device__ float g_WiT[MODES*4096];

// Grouped column layout c' = 0..31:
//   j = c'&7, odd = (c'>>3)&1, k = 2j+odd
//   c' 0..7: cos even k   8..15: cos odd   16..23: sin even   24..31: sin odd
__global__ void init_tables(const float* __restrict__ wr,
                            const float* __restrict__ wi) {
    int idx = blockIdx.x * blockDim.x + threadIdx.x;
    if (idx >= QN * 32) return;   // 65536 == basis entries == weight entries
    {   // basis
        int m = idx >> 5, c = idx & 31;
        int j = c & 7;
        int kk = 2 * j + ((c >> 3) & 1);
        int t = (kk * m) & (NN - 1);
        float a = (float)t * (1.0f / (float)HN);
        float v = (c < 16) ? cospif(a) : sinpif(a);
        g_FBi[idx] = v;
        g_FBf[idx] = (m == 0) ? 0.5f * v : v;  // m=0 quartet double-counts x[0],x[4096]
    }
    {   // weight transpose: wr[(i*64+o)*16+k] -> g_WrT[k][i*64+o]
        int io = idx >> 4, k = idx & 15;
        g_WrT[k * 4096 + io] = wr[idx];
        g_WiT[k * 4096 + io] = wi[idx];
    }
}

// ---------------------------------------------------------------------------
// Forward (folded): CS[row][c'] = sum_m combo_{cls}[row][m] * FBf[m][c']
// PROVEN (R11, 92.7us total): 64 rows/block, 128 threads, 4r x 4c tile.
// Inner: 2x LDS.128 + 16 FFMA, register double-buffered. KSPL=8 -> 512 blocks.
// Quartet {m, 4096-m, 4096+m, (8192-m)&8191} -> 4 class combos.
// ---------------------------------------------------------------------------
__global__ __launch_bounds__(128) void fwd_dft(const float* __restrict__ x) {
    __shared__ float  cmb[4 * CMB_S];     // 34.9 KB
    __shared__ float4 bs[32][8];          // 4 KB

    const int tid  = threadIdx.x;
    const int row0 = blockIdx.x * 64;
    const int ms0  = blockIdx.y * MSPL;
    const int tr   = tid >> 3;            // 0..15 -> rows 4*tr..4*tr+3
    const int tc   = tid & 7;             // 0..7  -> cols 4*tc..4*tc+3
    const int cls  = tc >> 1;             // 0..3

    float acc[4][4];
    #pragma unroll
    for (int j = 0; j < 4; j++)
        #pragma unroll
        for (int q = 0; q < 4; q++) acc[j][q] = 0.f;

    for (int ch = 0; ch < MSPL / 32; ch++) {
        const int m0 = ms0 + ch * 32;

        // stage combos: thread (row, g) covers m = g + 8*jj; conflict-free STS
        #pragma unroll
        for (int i = 0; i < 4; i++) {
            int q   = tid + i * 128;
            int row = q >> 3;
            int g   = q & 7;
            const float* xr = x + (size_t)(row0 + row) * NN;
            #pragma unroll
            for (int jj = 0; jj < 4; jj++) {
                int mi = g + 8 * jj;
                int mm = m0 + mi;
                float v0 = xr[mm];
                float v1 = xr[HN - mm];
                float v2 = xr[HN + mm];
                float v3 = xr[(NN - mm) & (NN - 1)];
                float p = v0 + v3, q2 = v0 - v3;
                float r = v1 + v2, s  = v2 - v1;
                float* base = cmb + mi * CMB_T + row;
                base[0 * CMB_S] = p + r;    // even-cos
                base[1 * CMB_S] = p - r;    // odd-cos
                base[2 * CMB_S] = q2 + s;   // even-sin
                base[3 * CMB_S] = q2 - s;   // odd-sin
            }
        }
        // stage basis tile (32 m x 32 c)
        #pragma unroll
        for (int i = 0; i < 2; i++) {
            int q  = tid + i * 128;
            int k  = q >> 3;
            int cq = q & 7;
            bs[k][cq] = *(const float4*)(g_FBf + (size_t)(m0 + k) * 32 + 4 * cq);
        }
        __syncthreads();

        const float* cbase = cmb + cls * CMB_S + 4 * tr;
        float4 xv = *(const float4*)(cbase);
        float4 bv = bs[0][tc];
        #pragma unroll
        for (int m = 0; m < 32; m++) {
            float4 xvn, bvn;
            if (m < 31) {                       // register double-buffer
                xvn = *(const float4*)(cbase + (m + 1) * CMB_T);
                bvn = bs[m + 1][tc];
            }
            acc[0][0] += xv.x * bv.x; acc[0][1] += xv.x * bv.y;
            acc[0][2] += xv.x * bv.z; acc[0][3] += xv.x * bv.w;
            acc[1][0] += xv.y * bv.x; acc[1][1] += xv.y * bv.y;
            acc[1][2] += xv.y * bv.z; acc[1][3] += xv.y * bv.w;
            acc[2][0] += xv.z * bv.x; acc[2][1] += xv.z * bv.y;
            acc[2][2] += xv.z * bv.z; acc[2][3] += xv.z * bv.w;
            acc[3][0] += xv.w * bv.x; acc[3][1] += xv.w * bv.y;
            acc[3][2] += xv.w * bv.z; acc[3][3] += xv.w * bv.w;
            xv = xvn; bv = bvn;
        }
        __syncthreads();
    }

    #pragma unroll
    for (int j = 0; j < 4; j++) {
        int rg = row0 + 4 * tr + j;
        float4 v = make_float4(acc[j][0], acc[j][1], acc[j][2], acc[j][3]);
        *(float4*)(g_partial + ((size_t)blockIdx.y * ROWS + rg) * 32 + 4 * tc) = v;
    }
}

// ---------------------------------------------------------------------------
// Reduce K-splits + m=2048 boundary term. Fully coalesced.
// ---------------------------------------------------------------------------
__global__ __launch_bounds__(256) void reduce_cs(const float* __restrict__ x) {
    int q = blockIdx.x * blockDim.x + threadIdx.x;
    if (q >= ROWS * 32) return;
    int row = q >> 5, c = q & 31;
    float s = 0.f;
    #pragma unroll
    for (int ks = 0; ks < KSPL; ks++)
        s += g_partial[(size_t)ks * ROWS * 32 + q];
    float xa = x[(size_t)row * NN + QN];
    float xb = x[(size_t)row * NN + 3 * QN];
    int j = c & 7;
    float sg = (j & 1) ? -1.f : 1.f;
    if (c < 8)        s += (xa + xb) * sg;
    else if (c >= 24) s += (xa - xb) * sg;
    g_CS[q] = s;
}

// ---------------------------------------------------------------------------
// Mix (proven): grid (16 k, 16 bg), 256 thr. Weights staged into smem with
// bulk coalesced float4 loads (high MLP), inner loop LDS-only.
// ---------------------------------------------------------------------------
__global__ __launch_bounds__(256) void mix() {
    __shared__ float sWr[64 * 64];
    __shared__ float sWi[64 * 64];
    __shared__ float sXc[256], sXs[256];
    const int k   = blockIdx.x;
    const int bg  = blockIdx.y;
    const int tid = threadIdx.x;

    const int cA = (k & 1) ? 8 + (k >> 1) : (k >> 1);
    const int cS = cA + 16;

    const float* wrk = g_WrT + (size_t)k * 4096;
    const float* wik = g_WiT + (size_t)k * 4096;
    #pragma unroll
    for (int i = 0; i < 4; i++) {
        int q = tid + i * 256;
        ((float4*)sWr)[q] = ((const float4*)wrk)[q];
        ((float4*)sWi)[q] = ((const float4*)wik)[q];
    }
    {   // (b_local = tid>>6, i = tid&63)
        int row = (bg * 4 + (tid >> 6)) * 64 + (tid & 63);
        sXc[tid] = g_CS[(size_t)row * 32 + cA];
        sXs[tid] = g_CS[(size_t)row * 32 + cS];
    }
    __syncthreads();

    const int o  = tid & 63;
    const int bl = tid >> 6;
    float cre = 0.f, cim = 0.f;
    #pragma unroll 8
    for (int i = 0; i < 64; i++) {
        float a   = sXc[bl * 64 + i];
        float s   = sXs[bl * 64 + i];
        float wre = sWr[i * 64 + o];
        float wim = sWi[i * 64 + o];
        cre += a * wre + s * wim;
        cim += a * wim - s * wre;
    }
    const float invN = 1.0f / (float)NN;
    float A  = (k == 0 ? cre : 2.f * cre) * invN;
    float Bc = (k == 0 ? 0.f : -2.f * cim * invN);
    int rowo = (bg * 4 + bl) * 64 + o;
    g_C2[(size_t)rowo * 32 + cA] = A;
    g_C2[(size_t)rowo * 32 + cS] = Bc;
}

// ---------------------------------------------------------------------------
// Inverse (folded): ONE n per thread (basis 32 regs -> ~75 total regs ->
// more resident blocks than the 110-reg 2-n version; occ ceiling ~50%).
// 128 thr, 32 rows/block -> 2048 blocks. Per row: 8 broadcast LDS.128 feed
// 32 FFMA -> 4 outputs, all 4 store streams warp-coalesced.
// n=0 wraps are exact duplicates (sin basis = 0); n==0 emits n=2048/6144.
// ---------------------------------------------------------------------------
__global__ __launch_bounds__(128) void inv_dft(float* __restrict__ y) {
    __shared__ float sC[32 * 32];
    const int tid  = threadIdx.x;
    const int row0 = blockIdx.y * 32;
    const int n    = blockIdx.x * 128 + tid;    // 0..2047

    #pragma unroll
    for (int i = 0; i < 2; i++) {
        int q = tid + i * 128;
        *(float4*)(sC + 4 * q) = *(const float4*)(g_C2 + (size_t)row0 * 32 + 4 * q);
    }

    float b[32];
    #pragma unroll
    for (int i = 0; i < 8; i++) {
        float4 v = *(const float4*)(g_FBi + (size_t)n * 32 + 4 * i);
        b[4*i+0] = v.x; b[4*i+1] = v.y; b[4*i+2] = v.z; b[4*i+3] = v.w;
    }
    __syncthreads();

    const int nrev = (NN - n) & (NN - 1);       // 0 when n==0 (dup, benign)
    const int nm   = HN - n, np = HN + n;

    for (int r = 0; r < 32; r++) {
        const float* cp = sC + r * 32;
        // a[0]=E (cos-even), a[1]=F (cos-odd), a[2]=G (sin-even), a[3]=H (sin-odd)
        float a[4] = {0.f, 0.f, 0.f, 0.f};
        #pragma unroll
        for (int i = 0; i < 8; i++) {
            float4 v = *(const float4*)(cp + 4 * i);   // broadcast LDS.128
            a[i >> 1] += v.x * b[4*i] + v.y * b[4*i+1]
                       + v.z * b[4*i+2] + v.w * b[4*i+3];
        }
        float P = a[0] + a[1], Q = a[0] - a[1];
        float R = a[2] + a[3], S = a[2] - a[3];
        size_t rb = (size_t)(row0 + r) * NN;

        y[rb + n]    = P + R;
        y[rb + nrev] = P - R;        // n==0: dup of y[0] (R==0), benign
        y[rb + nm]   = Q - S;        // n==0: dup of np (S==0), benign
        y[rb + np]   = Q + S;

        if (n == 0) {   // outputs n=2048, 6144
            float da = 0.f, db = 0.f;
            #pragma unroll
            for (int i = 0; i < 8; i++) {
                float sg = (i & 1) ? -1.f : 1.f;
                da += sg * cp[i];        // A_{2j} * (-1)^j
                db += sg * cp[24 + i];   // B_{2j+1} * (-1)^j
            }
            y[rb + QN]     = da + db;
            y[rb + 3 * QN] = da - db;
        }
    }
}

// ---------------------------------------------------------------------------
extern "C" void kernel_launch(void* const* d_in, const int* in_sizes, int n_in,
                              void* d_out, int out_size) {
    const float* x  = (const float*)d_in[0];
    const float* wr = (const float*)d_in[1];
    const float* wi = (const float*)d_in[2];
    float*       y  = (float*)d_out;

    init_tables<<<(QN * 32 + 255) / 256, 256>>>(wr, wi);
    fwd_dft<<<dim3(ROWS / 64, KSPL), 128>>>(x);
    reduce_cs<<<(ROWS * 32 + 255) / 256, 256>>>(x);
    mix<<<dim3(MODES, 16), 256>>>();
    inv_dft<<<dim3(QN / 128, ROWS / 32), 128>>>(y);
}